// round 3
// baseline (speedup 1.0000x reference)
#include <cuda_runtime.h>

#define N_RAYS   (1 << 20)
#define T_ITERS  4
#define NPTS     8
#define DIM      64
#define IN_DIM   24
#define INF_F    1e9f

typedef unsigned long long ull;

// ---- packed f32x2 helpers (Blackwell fp32x2 path: 2x scalar FFMA throughput) ----
__device__ __forceinline__ ull pack2(float lo, float hi) {
    ull r; asm("mov.b64 %0, {%1, %2};" : "=l"(r) : "f"(lo), "f"(hi)); return r;
}
__device__ __forceinline__ void unpack2(ull v, float& lo, float& hi) {
    asm("mov.b64 {%0, %1}, %2;" : "=f"(lo), "=f"(hi) : "l"(v));
}
__device__ __forceinline__ void fma2(ull& d, ull a, ull b) {
    asm("fma.rn.f32x2 %0, %1, %2, %0;" : "+l"(d) : "l"(a), "l"(b));
}

struct __align__(16) SmemWeights {
    float  W0[IN_DIM][DIM];     // 6 KB
    float  Ws[2][DIM][DIM];     // 32 KB
    float  b0[DIM];
    float  bs[2][DIM];
    float  g[2][DIM];
    float  beta[2][DIM];
    float2 head[DIM];           // {Wc[k], Wd[k]} interleaved for packed head fma
    float  isc[3];
    float  off[3];
    float  bc, bd;
};

__global__ __launch_bounds__(128) void nbvh_kernel(
    const float* __restrict__ orig, const float* __restrict__ vec,
    const unsigned int* __restrict__ masks,   // bool materialized as 4-byte words
    const float* __restrict__ t1, const float* __restrict__ t2,
    const float* __restrict__ mesh_min, const float* __restrict__ mesh_max,
    const float* __restrict__ W0, const float* __restrict__ b0,
    const float* __restrict__ ln_g, const float* __restrict__ ln_b,
    const float* __restrict__ Ws, const float* __restrict__ bs,
    const float* __restrict__ Wc, const float* __restrict__ bc,
    const float* __restrict__ Wd, const float* __restrict__ bd,
    float* __restrict__ out, int two_part)
{
    __shared__ SmemWeights sm;
    const int tid = threadIdx.x;

    // ---- cooperative weight staging ----
    for (int i = tid; i < IN_DIM * DIM; i += blockDim.x) ((float*)sm.W0)[i] = W0[i];
    for (int i = tid; i < 2 * DIM * DIM; i += blockDim.x) ((float*)sm.Ws)[i] = Ws[i];
    for (int i = tid; i < DIM; i += blockDim.x) {
        sm.b0[i]   = b0[i];
        sm.head[i] = make_float2(Wc[i], Wd[i]);
    }
    for (int i = tid; i < 2 * DIM; i += blockDim.x) {
        ((float*)sm.bs)[i]   = bs[i];
        ((float*)sm.g)[i]    = ln_g[i];
        ((float*)sm.beta)[i] = ln_b[i];
    }
    if (tid < 3) {
        float mn = mesh_min[tid], mx = mesh_max[tid];
        float min_infl = mn - 0.5f * (mx - mn);
        float scale    = 2.0f * (mx - mn);     // max_infl - min_infl
        float is       = 1.0f / scale;
        sm.isc[tid] = is;
        sm.off[tid] = -min_infl * is;          // x*isc + off == (x - min_infl)/scale
    }
    if (tid == 0) { sm.bc = bc[0]; sm.bd = bd[0]; }
    __syncthreads();

    const int r = blockIdx.x * blockDim.x + tid;
    if (r >= N_RAYS) return;

    const float o0 = orig[3 * r], o1 = orig[3 * r + 1], o2 = orig[3 * r + 2];
    const float v0 = vec[3 * r],  v1 = vec[3 * r + 1],  v2 = vec[3 * r + 2];
    const float iscx = sm.isc[0], iscy = sm.isc[1], iscz = sm.isc[2];
    const float offx = sm.off[0], offy = sm.off[1], offz = sm.off[2];
    const ull hbias = pack2(sm.bc, sm.bd);

    float dist = INF_F;

    #pragma unroll 1
    for (int it = 0; it < T_ITERS; ++it) {
        const bool  m   = masks[it * N_RAYS + r] != 0u;  // nonzero test: works for int32 1 or float32 1.0
        const float ct1 = t1[it * N_RAYS + r];
        const float ct2 = t2[it * N_RAYS + r];

        const float po0 = fmaf(v0, ct1, o0);
        const float po1 = fmaf(v1, ct1, o1);
        const float po2 = fmaf(v2, ct1, o2);
        const float dt  = ct2 - ct1;
        const float pv0 = v0 * dt, pv1 = v1 * dt, pv2 = v2 * dt;

        // ---- build normalized 24-d input ----
        float x[IN_DIM];
        #pragma unroll
        for (int k = 0; k < NPTS; ++k) {
            const float t = (float)k * (1.0f / 7.0f);
            const float px = fmaf(pv0, t, po0);
            const float py = fmaf(pv1, t, po1);
            const float pz = fmaf(pv2, t, po2);
            x[3 * k + 0] = fmaf(px, iscx, offx);
            x[3 * k + 1] = fmaf(py, iscy, offy);
            x[3 * k + 2] = fmaf(pz, iscz, offz);
        }

        // ---- layer 0: [24] @ W0[24,64] + b0 ----
        ull acc[DIM / 2];
        {
            const ull* bb = (const ull*)sm.b0;
            #pragma unroll
            for (int q = 0; q < DIM / 2; ++q) acc[q] = bb[q];
        }
        #pragma unroll
        for (int k = 0; k < IN_DIM; ++k) {
            const ull a = pack2(x[k], x[k]);
            const ulonglong2* w = (const ulonglong2*)sm.W0[k];
            #pragma unroll
            for (int q = 0; q < 16; ++q) {
                const ulonglong2 ww = w[q];
                fma2(acc[2 * q + 0], a, ww.x);
                fma2(acc[2 * q + 1], a, ww.y);
            }
        }
        float act[DIM];
        #pragma unroll
        for (int q = 0; q < DIM / 2; ++q) unpack2(acc[q], act[2 * q], act[2 * q + 1]);

        // ---- 2 hidden layers: relu -> layernorm -> matmul ----
        #pragma unroll 1
        for (int L = 0; L < 2; ++L) {
            float mu = 0.f;
            #pragma unroll
            for (int k = 0; k < DIM; ++k) { act[k] = fmaxf(act[k], 0.f); mu += act[k]; }
            mu *= (1.0f / DIM);
            float var = 0.f;
            #pragma unroll
            for (int k = 0; k < DIM; ++k) { const float d = act[k] - mu; var = fmaf(d, d, var); }
            var *= (1.0f / DIM);
            const float rs = rsqrtf(var + 1e-5f);
            #pragma unroll
            for (int k = 0; k < DIM; ++k)
                act[k] = fmaf((act[k] - mu) * rs, sm.g[L][k], sm.beta[L][k]);

            const ull* bb = (const ull*)sm.bs[L];
            #pragma unroll
            for (int q = 0; q < DIM / 2; ++q) acc[q] = bb[q];
            #pragma unroll
            for (int k = 0; k < DIM; ++k) {
                const ull a = pack2(act[k], act[k]);
                const ulonglong2* w = (const ulonglong2*)sm.Ws[L][k];
                #pragma unroll
                for (int q = 0; q < 16; ++q) {
                    const ulonglong2 ww = w[q];
                    fma2(acc[2 * q + 0], a, ww.x);
                    fma2(acc[2 * q + 1], a, ww.y);
                }
            }
            #pragma unroll
            for (int q = 0; q < DIM / 2; ++q) unpack2(acc[q], act[2 * q], act[2 * q + 1]);
        }

        // ---- final relu + two heads as one packed dot ----
        ull h = hbias;
        const ull* hw = (const ull*)sm.head;
        #pragma unroll
        for (int k = 0; k < DIM; ++k) {
            const float a = fmaxf(act[k], 0.f);
            fma2(h, pack2(a, a), hw[k]);
        }
        float cls, dvc;
        unpack2(h, cls, dvc);

        // upd = mask & (hit>0) & (dv < dist); dv = dvc + ct1
        if (m && cls > 0.f) {
            const float dv = dvc + ct1;
            if (dv < dist) dist = dv;
        }
    }

    if (dist == INF_F) dist = 0.f;
    if (two_part) {
        out[r]          = (dist > 0.f) ? 1.f : 0.f;
        out[N_RAYS + r] = dist;
    } else {
        out[r] = dist;
    }
}

extern "C" void kernel_launch(void* const* d_in, const int* in_sizes, int n_in,
                              void* d_out, int out_size) {
    const float* orig      = (const float*)d_in[0];
    const float* vec       = (const float*)d_in[1];
    const unsigned int* masks = (const unsigned int*)d_in[2];   // bool[T,N] as 4-byte words
    /* d_in[3] = bbox_idxs (unused by reference) */
    const float* t1        = (const float*)d_in[4];
    const float* t2        = (const float*)d_in[5];
    const float* mesh_min  = (const float*)d_in[6];
    const float* mesh_max  = (const float*)d_in[7];
    const float* W0        = (const float*)d_in[8];
    const float* b0        = (const float*)d_in[9];
    const float* ln_g      = (const float*)d_in[10];
    const float* ln_b      = (const float*)d_in[11];
    const float* Ws        = (const float*)d_in[12];
    const float* bs        = (const float*)d_in[13];
    const float* Wc        = (const float*)d_in[14];
    const float* bc        = (const float*)d_in[15];
    const float* Wd        = (const float*)d_in[16];
    const float* bd        = (const float*)d_in[17];

    const int two_part = (out_size >= 2 * N_RAYS) ? 1 : 0;

    nbvh_kernel<<<N_RAYS / 128, 128>>>(
        orig, vec, masks, t1, t2, mesh_min, mesh_max,
        W0, b0, ln_g, ln_b, Ws, bs, Wc, bc, Wd, bd,
        (float*)d_out, two_part);
}